// round 9
// baseline (speedup 1.0000x reference)
#include <cuda_runtime.h>
#include <cstdint>

// Problem constants (dataset-fixed): B=64, T=512, F=1024, H=31, G=4H=124
#define B_SZ 64
#define T_SZ 512
#define F_SZ 1024
#define H_SZ 31
#define G_SZ 124
#define ROWS (B_SZ * T_SZ)      // 32768
#define XG_STRIDE 128           // padded gate stride
#define FULLM 0xffffffffu

// ---------------- scratch (no allocations allowed) ----------------
__device__ float g_xg[(size_t)ROWS * XG_STRIDE];      // gates1 x-part + bias
__device__ float g_h2hist[(size_t)ROWS * 32];         // h2 per step, [b*T+t][32]

// ---------------- fast activations (MUFU; proven accuracy-harmless) -------
__device__ __forceinline__ float sigf(float x) {
    return __fdividef(1.0f, 1.0f + __expf(-x));
}
__device__ __forceinline__ float tanh_f(float x) {
    return fmaf(2.0f, sigf(2.0f * x), -1.0f);
}

// =================================================================
// Kernel 1: xg[r][g] = x_r . W_ih1[g,:] + b_ih1[g] + b_hh1[g]
// (unchanged from R8: 238us measured)
// =================================================================
__global__ __launch_bounds__(256) void gemm_xg_kernel(
    const float* __restrict__ x, const float* __restrict__ W,
    const float* __restrict__ b_ih, const float* __restrict__ b_hh) {
    __shared__ float xs[16][128];
    __shared__ float ws[16][128];

    const int tid = threadIdx.x;
    const int row0 = blockIdx.x * 128;
    const int tx = tid & 15;
    const int ty = tid >> 4;
    const int c0 = tx * 8;
    const int r0 = ty * 8;

    float acc[8][8];
#pragma unroll
    for (int i = 0; i < 8; i++)
#pragma unroll
        for (int j = 0; j < 8; j++) acc[i][j] = 0.f;

    for (int k0 = 0; k0 < F_SZ; k0 += 16) {
#pragma unroll
        for (int l = tid; l < 512; l += 256) {
            int r = l >> 2;
            int kq = (l & 3) << 2;
            float4 v = *(const float4*)(x + (size_t)(row0 + r) * F_SZ + k0 + kq);
            xs[kq + 0][r] = v.x; xs[kq + 1][r] = v.y;
            xs[kq + 2][r] = v.z; xs[kq + 3][r] = v.w;
        }
#pragma unroll
        for (int l = tid; l < 512; l += 256) {
            int gc = l >> 2;
            int kq = (l & 3) << 2;
            float4 v = make_float4(0.f, 0.f, 0.f, 0.f);
            if (gc < G_SZ) v = *(const float4*)(W + (size_t)gc * F_SZ + k0 + kq);
            ws[kq + 0][gc] = v.x; ws[kq + 1][gc] = v.y;
            ws[kq + 2][gc] = v.z; ws[kq + 3][gc] = v.w;
        }
        __syncthreads();

#pragma unroll
        for (int kk = 0; kk < 16; kk++) {
            float4 xa = *(const float4*)&xs[kk][r0];
            float4 xb = *(const float4*)&xs[kk][r0 + 4];
            float4 wa = *(const float4*)&ws[kk][c0];
            float4 wb = *(const float4*)&ws[kk][c0 + 4];
            float xr[8] = {xa.x, xa.y, xa.z, xa.w, xb.x, xb.y, xb.z, xb.w};
            float wr[8] = {wa.x, wa.y, wa.z, wa.w, wb.x, wb.y, wb.z, wb.w};
#pragma unroll
            for (int i = 0; i < 8; i++)
#pragma unroll
                for (int j = 0; j < 8; j++)
                    acc[i][j] = fmaf(xr[i], wr[j], acc[i][j]);
        }
        __syncthreads();
    }

    float bs[8];
#pragma unroll
    for (int j = 0; j < 8; j++) {
        int cc = c0 + j;
        bs[j] = (cc < G_SZ) ? (b_ih[cc] + b_hh[cc]) : 0.f;
    }
#pragma unroll
    for (int i = 0; i < 8; i++) {
        int r = row0 + r0 + i;
        float4 lo = make_float4(acc[i][0] + bs[0], acc[i][1] + bs[1],
                                acc[i][2] + bs[2], acc[i][3] + bs[3]);
        float4 hi = make_float4(acc[i][4] + bs[4], acc[i][5] + bs[5],
                                acc[i][6] + bs[6], acc[i][7] + bs[7]);
        *(float4*)&g_xg[(size_t)r * XG_STRIDE + c0] = lo;
        *(float4*)&g_xg[(size_t)r * XG_STRIDE + c0 + 4] = hi;
    }
}

// =================================================================
// Kernel 2: recurrence, WARP-PER-BATCH, barrier-free.
// Lane = unit; each lane owns all 4 gates of its unit (in-lane LSTM
// pointwise). h states in registers, broadcast via shfl. Weights in
// smem, [k][unit][4gates] layout -> conflict-free LDS.128.
// 4 warps (=4 batches) per block, 16 blocks.
// =================================================================
#define ROFF_WHH1 0                      // [(k*32+u)*4+q], 4096
#define ROFF_WIH2 4096
#define ROFF_WHH2 8192
#define ROFF_WLIN 12288                  // [k*1024+f], 32768
#define ROFF_BLIN 45056                  // 1024
#define ROFF_XCUR 46080                  // 4 warps x 1024
#define RSM_FLOATS 50176
#define RSM_BYTES (RSM_FLOATS * 4)       // 200704 B

__global__ __launch_bounds__(128, 1) void recurrence_kernel(
    const float* __restrict__ W_hh1, const float* __restrict__ W_ih2,
    const float* __restrict__ W_hh2, const float* __restrict__ b_ih2,
    const float* __restrict__ b_hh2, const float* __restrict__ W_ih1,
    const float* __restrict__ b_ih1, const float* __restrict__ b_hh1,
    const float* __restrict__ W_lin, const float* __restrict__ b_lin,
    float* __restrict__ out, int Tout, int future) {
    extern __shared__ float sm[];
    float* whh1s = sm + ROFF_WHH1;
    float* wih2s = sm + ROFF_WIH2;
    float* whh2s = sm + ROFF_WHH2;
    float* wlint = sm + ROFF_WLIN;
    float* blins = sm + ROFF_BLIN;

    const int tid = threadIdx.x;
    const int wid = tid >> 5;
    const int lane = tid & 31;
    const int b = blockIdx.x * 4 + wid;
    float* xcur = sm + ROFF_XCUR + wid * 1024;

    // ---- one-time smem fills (all 128 threads) ----
    for (int i = tid; i < 1024; i += 128) {
        int k = i >> 5, u = i & 31;
        float4 a = make_float4(0.f, 0.f, 0.f, 0.f);
        float4 c = a, d = a;
        if (k < H_SZ && u < H_SZ) {
            a = make_float4(W_hh1[u * H_SZ + k], W_hh1[(31 + u) * H_SZ + k],
                            W_hh1[(62 + u) * H_SZ + k], W_hh1[(93 + u) * H_SZ + k]);
            c = make_float4(W_ih2[u * H_SZ + k], W_ih2[(31 + u) * H_SZ + k],
                            W_ih2[(62 + u) * H_SZ + k], W_ih2[(93 + u) * H_SZ + k]);
            d = make_float4(W_hh2[u * H_SZ + k], W_hh2[(31 + u) * H_SZ + k],
                            W_hh2[(62 + u) * H_SZ + k], W_hh2[(93 + u) * H_SZ + k]);
        }
        *(float4*)&whh1s[i * 4] = a;
        *(float4*)&wih2s[i * 4] = c;
        *(float4*)&whh2s[i * 4] = d;
    }
    for (int i = tid; i < 32 * 1024; i += 128) {
        int k = i >> 10, f = i & 1023;
        wlint[i] = (k < H_SZ) ? W_lin[f * H_SZ + k] : 0.f;
    }
    for (int i = tid; i < 1024; i += 128) blins[i] = b_lin[i];
    __syncthreads();   // ONLY block-wide barrier in the kernel

    float4 b1q = make_float4(0.f, 0.f, 0.f, 0.f);
    float4 b2q = b1q;
    if (lane < H_SZ) {
        b1q = make_float4(b_ih1[lane] + b_hh1[lane], b_ih1[31 + lane] + b_hh1[31 + lane],
                          b_ih1[62 + lane] + b_hh1[62 + lane], b_ih1[93 + lane] + b_hh1[93 + lane]);
        b2q = make_float4(b_ih2[lane] + b_hh2[lane], b_ih2[31 + lane] + b_hh2[31 + lane],
                          b_ih2[62 + lane] + b_hh2[62 + lane], b_ih2[93 + lane] + b_hh2[93 + lane]);
    }

    float h1 = 0.f, h2 = 0.f, c1 = 0.f, c2 = 0.f;
    const float* xgb = g_xg + (size_t)b * T_SZ * XG_STRIDE;

    float cur0 = __ldcg(xgb + lane);
    float cur1 = __ldcg(xgb + 31 + lane);
    float cur2 = __ldcg(xgb + 62 + lane);
    float cur3 = __ldcg(xgb + 93 + lane);

    // ---------------- teacher-forced recurrence (sync-free) ----------------
    for (int t = 0; t < T_SZ; t++) {
        float n0 = 0.f, n1 = 0.f, n2 = 0.f, n3 = 0.f;
        if (t < T_SZ - 1) {
            const float* p = xgb + (size_t)(t + 1) * XG_STRIDE;
            n0 = __ldcg(p + lane);      n1 = __ldcg(p + 31 + lane);
            n2 = __ldcg(p + 62 + lane); n3 = __ldcg(p + 93 + lane);
        }

        // layer 1
        float ai = cur0, af = cur1, ag = cur2, ao = cur3;
#pragma unroll
        for (int k = 0; k < H_SZ; k++) {
            float hk = __shfl_sync(FULLM, h1, k);
            float4 w = *(const float4*)&whh1s[(k * 32 + lane) * 4];
            ai = fmaf(w.x, hk, ai); af = fmaf(w.y, hk, af);
            ag = fmaf(w.z, hk, ag); ao = fmaf(w.w, hk, ao);
        }
        {
            float is = sigf(ai), fs = sigf(af), gg = tanh_f(ag), os = sigf(ao);
            c1 = fs * c1 + is * gg;
            h1 = os * tanh_f(c1);
        }

        // layer 2
        ai = b2q.x; af = b2q.y; ag = b2q.z; ao = b2q.w;
#pragma unroll
        for (int k = 0; k < H_SZ; k++) {
            float h1k = __shfl_sync(FULLM, h1, k);
            float h2k = __shfl_sync(FULLM, h2, k);
            float4 wa = *(const float4*)&wih2s[(k * 32 + lane) * 4];
            float4 wb = *(const float4*)&whh2s[(k * 32 + lane) * 4];
            ai = fmaf(wa.x, h1k, fmaf(wb.x, h2k, ai));
            af = fmaf(wa.y, h1k, fmaf(wb.y, h2k, af));
            ag = fmaf(wa.z, h1k, fmaf(wb.z, h2k, ag));
            ao = fmaf(wa.w, h1k, fmaf(wb.w, h2k, ao));
        }
        {
            float is = sigf(ai), fs = sigf(af), gg = tanh_f(ag), os = sigf(ao);
            c2 = fs * c2 + is * gg;
            h2 = os * tanh_f(c2);
        }
        if (lane < H_SZ) g_h2hist[((size_t)b * T_SZ + t) * 32 + lane] = h2;

        cur0 = n0; cur1 = n1; cur2 = n2; cur3 = n3;
    }

    // ---------------- autoregressive future (warp-local) ----------------
    // projection: lane covers f = 4*lane + 128*m, m=0..7 (conflict-free)
    {
        float4 acc[8];
#pragma unroll
        for (int m = 0; m < 8; m++) acc[m] = *(const float4*)&blins[128 * m + 4 * lane];
#pragma unroll
        for (int k = 0; k < H_SZ; k++) {
            float h2k = __shfl_sync(FULLM, h2, k);
#pragma unroll
            for (int m = 0; m < 8; m++) {
                float4 w = *(const float4*)&wlint[k * 1024 + 128 * m + 4 * lane];
                acc[m].x = fmaf(w.x, h2k, acc[m].x);
                acc[m].y = fmaf(w.y, h2k, acc[m].y);
                acc[m].z = fmaf(w.z, h2k, acc[m].z);
                acc[m].w = fmaf(w.w, h2k, acc[m].w);
            }
        }
#pragma unroll
        for (int m = 0; m < 8; m++) *(float4*)&xcur[128 * m + 4 * lane] = acc[m];
    }
    __syncwarp();

    for (int s = 1; s <= future; s++) {
        // layer-1 gates: b1 + W_hh1.h1 + W_ih1.xcur
        float ai = b1q.x, af = b1q.y, ag = b1q.z, ao = b1q.w;
#pragma unroll
        for (int k = 0; k < H_SZ; k++) {
            float hk = __shfl_sync(FULLM, h1, k);
            float4 w = *(const float4*)&whh1s[(k * 32 + lane) * 4];
            ai = fmaf(w.x, hk, ai); af = fmaf(w.y, hk, af);
            ag = fmaf(w.z, hk, ag); ao = fmaf(w.w, hk, ao);
        }
        if (lane < H_SZ) {
            const float4* r0 = (const float4*)(W_ih1 + (size_t)(lane) * F_SZ);
            const float4* r1 = (const float4*)(W_ih1 + (size_t)(31 + lane) * F_SZ);
            const float4* r2 = (const float4*)(W_ih1 + (size_t)(62 + lane) * F_SZ);
            const float4* r3 = (const float4*)(W_ih1 + (size_t)(93 + lane) * F_SZ);
            const float4* x4 = (const float4*)xcur;
            float s0 = 0.f, s1 = 0.f, s2 = 0.f, s3 = 0.f;
#pragma unroll 4
            for (int p = 0; p < 256; p++) {
                float4 xv = x4[p];
                float4 w0 = __ldcg(r0 + p);
                float4 w1 = __ldcg(r1 + p);
                float4 w2 = __ldcg(r2 + p);
                float4 w3 = __ldcg(r3 + p);
                s0 = fmaf(w0.x, xv.x, fmaf(w0.y, xv.y, fmaf(w0.z, xv.z, fmaf(w0.w, xv.w, s0))));
                s1 = fmaf(w1.x, xv.x, fmaf(w1.y, xv.y, fmaf(w1.z, xv.z, fmaf(w1.w, xv.w, s1))));
                s2 = fmaf(w2.x, xv.x, fmaf(w2.y, xv.y, fmaf(w2.z, xv.z, fmaf(w2.w, xv.w, s2))));
                s3 = fmaf(w3.x, xv.x, fmaf(w3.y, xv.y, fmaf(w3.z, xv.z, fmaf(w3.w, xv.w, s3))));
            }
            ai += s0; af += s1; ag += s2; ao += s3;
        }
        {
            float is = sigf(ai), fs = sigf(af), gg = tanh_f(ag), os = sigf(ao);
            c1 = fs * c1 + is * gg;
            h1 = os * tanh_f(c1);
        }

        // layer 2
        ai = b2q.x; af = b2q.y; ag = b2q.z; ao = b2q.w;
#pragma unroll
        for (int k = 0; k < H_SZ; k++) {
            float h1k = __shfl_sync(FULLM, h1, k);
            float h2k = __shfl_sync(FULLM, h2, k);
            float4 wa = *(const float4*)&wih2s[(k * 32 + lane) * 4];
            float4 wb = *(const float4*)&whh2s[(k * 32 + lane) * 4];
            ai = fmaf(wa.x, h1k, fmaf(wb.x, h2k, ai));
            af = fmaf(wa.y, h1k, fmaf(wb.y, h2k, af));
            ag = fmaf(wa.z, h1k, fmaf(wb.z, h2k, ag));
            ao = fmaf(wa.w, h1k, fmaf(wb.w, h2k, ao));
        }
        {
            float is = sigf(ai), fs = sigf(af), gg = tanh_f(ag), os = sigf(ao);
            c2 = fs * c2 + is * gg;
            h2 = os * tanh_f(c2);
        }
        __syncwarp();

        // projection -> out row 511+s, and next xcur
        {
            float4 acc[8];
#pragma unroll
            for (int m = 0; m < 8; m++) acc[m] = *(const float4*)&blins[128 * m + 4 * lane];
#pragma unroll
            for (int k = 0; k < H_SZ; k++) {
                float h2k = __shfl_sync(FULLM, h2, k);
#pragma unroll
                for (int m = 0; m < 8; m++) {
                    float4 w = *(const float4*)&wlint[k * 1024 + 128 * m + 4 * lane];
                    acc[m].x = fmaf(w.x, h2k, acc[m].x);
                    acc[m].y = fmaf(w.y, h2k, acc[m].y);
                    acc[m].z = fmaf(w.z, h2k, acc[m].z);
                    acc[m].w = fmaf(w.w, h2k, acc[m].w);
                }
            }
            float* orow = out + ((size_t)b * Tout + (T_SZ - 1) + s) * F_SZ;
#pragma unroll
            for (int m = 0; m < 8; m++) {
                *(float4*)&xcur[128 * m + 4 * lane] = acc[m];
                *(float4*)&orow[128 * m + 4 * lane] = acc[m];
            }
        }
        __syncwarp();
    }
}

// =================================================================
// Kernel 3: teacher-forced output projection (unchanged)
// =================================================================
__global__ __launch_bounds__(256) void outproj_kernel(
    const float* __restrict__ W_lin, const float* __restrict__ b_lin,
    float* __restrict__ out, int Tout) {
    __shared__ float h2t[16][32];
    const int b = blockIdx.y;
    const int t0 = blockIdx.x * 16;
    const int tid = threadIdx.x;

    const float* src = g_h2hist + ((size_t)b * T_SZ + t0) * 32;
    for (int i = tid; i < 512; i += 256) ((float*)h2t)[i] = src[i];
    __syncthreads();

#pragma unroll
    for (int c = 0; c < 4; c++) {
        int f = tid + c * 256;
        float w[31];
        const float* wrow = W_lin + (size_t)f * 31;
#pragma unroll
        for (int k = 0; k < 31; k++) w[k] = wrow[k];
        float bv = b_lin[f];
#pragma unroll
        for (int tt = 0; tt < 16; tt++) {
            const float4* hp = (const float4*)&h2t[tt][0];
            float a0 = bv, a1 = 0.f, a2 = 0.f, a3 = 0.f;
#pragma unroll
            for (int p = 0; p < 7; p++) {
                float4 h = hp[p];
                a0 = fmaf(w[4 * p + 0], h.x, a0);
                a1 = fmaf(w[4 * p + 1], h.y, a1);
                a2 = fmaf(w[4 * p + 2], h.z, a2);
                a3 = fmaf(w[4 * p + 3], h.w, a3);
            }
            a0 = fmaf(w[28], h2t[tt][28], a0);
            a1 = fmaf(w[29], h2t[tt][29], a1);
            a2 = fmaf(w[30], h2t[tt][30], a2);
            out[((size_t)b * Tout + t0 + tt) * F_SZ + f] = (a0 + a1) + (a2 + a3);
        }
    }
}

// =================================================================
extern "C" void kernel_launch(void* const* d_in, const int* in_sizes, int n_in,
                              void* d_out, int out_size) {
    const float* input = (const float*)d_in[0];
    const float* W_ih1 = (const float*)d_in[1];
    const float* W_hh1 = (const float*)d_in[2];
    const float* b_ih1 = (const float*)d_in[3];
    const float* b_hh1 = (const float*)d_in[4];
    const float* W_ih2 = (const float*)d_in[5];
    const float* W_hh2 = (const float*)d_in[6];
    const float* b_ih2 = (const float*)d_in[7];
    const float* b_hh2 = (const float*)d_in[8];
    const float* W_lin = (const float*)d_in[9];
    const float* b_lin = (const float*)d_in[10];
    float* out = (float*)d_out;

    const int Tout = out_size / (B_SZ * F_SZ);   // 528
    const int future = Tout - T_SZ;              // 16

    cudaFuncSetAttribute(recurrence_kernel,
                         cudaFuncAttributeMaxDynamicSharedMemorySize, RSM_BYTES);

    gemm_xg_kernel<<<ROWS / 128, 256>>>(input, W_ih1, b_ih1, b_hh1);

    recurrence_kernel<<<B_SZ / 4, 128, RSM_BYTES>>>(
        W_hh1, W_ih2, W_hh2, b_ih2, b_hh2, W_ih1, b_ih1, b_hh1,
        W_lin, b_lin, out, Tout, future);

    dim3 g3(T_SZ / 16, B_SZ);
    outproj_kernel<<<g3, 256>>>(W_lin, b_lin, out, Tout);
}

// round 10
// speedup vs baseline: 1.7102x; 1.7102x over previous
#include <cuda_runtime.h>
#include <cstdint>

// Problem constants (dataset-fixed): B=64, T=512, F=1024, H=31, G=4H=124
#define B_SZ 64
#define T_SZ 512
#define F_SZ 1024
#define H_SZ 31
#define G_SZ 124
#define ROWS (B_SZ * T_SZ)      // 32768
#define XG_STRIDE 128           // padded gate stride
#define FULLM 0xffffffffu

// ---------------- scratch (no allocations allowed) ----------------
__device__ float g_xg[(size_t)ROWS * XG_STRIDE];      // gates1 x-part + bias
__device__ float g_h2hist[(size_t)ROWS * 32];         // h2 per step
__device__ float g_state[B_SZ][4][32];                // h1,c1,h2,c2 handoff

// ---------------- fast activations (MUFU; proven accuracy-harmless) -------
__device__ __forceinline__ float sigf(float x) {
    return __fdividef(1.0f, 1.0f + __expf(-x));
}
__device__ __forceinline__ float tanh_f(float x) {
    return fmaf(2.0f, sigf(2.0f * x), -1.0f);
}

// 32-wide dot: register weights (w[31]=0) x float4 broadcast smem h
__device__ __forceinline__ float dot32q(const float* __restrict__ w,
                                        const float* __restrict__ h) {
    float a0 = 0.f, a1 = 0.f, a2 = 0.f, a3 = 0.f;
#pragma unroll
    for (int k = 0; k < 32; k += 4) {
        float4 hv = *(const float4*)(h + k);   // LDS.128 broadcast
        a0 = fmaf(w[k + 0], hv.x, a0);
        a1 = fmaf(w[k + 1], hv.y, a1);
        a2 = fmaf(w[k + 2], hv.z, a2);
        a3 = fmaf(w[k + 3], hv.w, a3);
    }
    return (a0 + a1) + (a2 + a3);
}

// LSTM pointwise via intra-quad shuffles; every lane of the quad keeps c.
__device__ __forceinline__ float lstm_unit(float myg, int lanebase, float& c) {
    float vi = __shfl_sync(FULLM, myg, lanebase + 0);
    float vf = __shfl_sync(FULLM, myg, lanebase + 1);
    float vg = __shfl_sync(FULLM, myg, lanebase + 2);
    float vo = __shfl_sync(FULLM, myg, lanebase + 3);
    c = vf * c + vi * vg;
    return vo * tanh_f(c);
}

// =================================================================
// Kernel 1: xg[r][g] = x_r . W_ih1[g,:] + b_ih1[g] + b_hh1[g]
// (unchanged; 238us measured)
// =================================================================
__global__ __launch_bounds__(256) void gemm_xg_kernel(
    const float* __restrict__ x, const float* __restrict__ W,
    const float* __restrict__ b_ih, const float* __restrict__ b_hh) {
    __shared__ float xs[16][128];
    __shared__ float ws[16][128];

    const int tid = threadIdx.x;
    const int row0 = blockIdx.x * 128;
    const int tx = tid & 15;
    const int ty = tid >> 4;
    const int c0 = tx * 8;
    const int r0 = ty * 8;

    float acc[8][8];
#pragma unroll
    for (int i = 0; i < 8; i++)
#pragma unroll
        for (int j = 0; j < 8; j++) acc[i][j] = 0.f;

    for (int k0 = 0; k0 < F_SZ; k0 += 16) {
#pragma unroll
        for (int l = tid; l < 512; l += 256) {
            int r = l >> 2;
            int kq = (l & 3) << 2;
            float4 v = *(const float4*)(x + (size_t)(row0 + r) * F_SZ + k0 + kq);
            xs[kq + 0][r] = v.x; xs[kq + 1][r] = v.y;
            xs[kq + 2][r] = v.z; xs[kq + 3][r] = v.w;
        }
#pragma unroll
        for (int l = tid; l < 512; l += 256) {
            int gc = l >> 2;
            int kq = (l & 3) << 2;
            float4 v = make_float4(0.f, 0.f, 0.f, 0.f);
            if (gc < G_SZ) v = *(const float4*)(W + (size_t)gc * F_SZ + k0 + kq);
            ws[kq + 0][gc] = v.x; ws[kq + 1][gc] = v.y;
            ws[kq + 2][gc] = v.z; ws[kq + 3][gc] = v.w;
        }
        __syncthreads();

#pragma unroll
        for (int kk = 0; kk < 16; kk++) {
            float4 xa = *(const float4*)&xs[kk][r0];
            float4 xb = *(const float4*)&xs[kk][r0 + 4];
            float4 wa = *(const float4*)&ws[kk][c0];
            float4 wb = *(const float4*)&ws[kk][c0 + 4];
            float xr[8] = {xa.x, xa.y, xa.z, xa.w, xb.x, xb.y, xb.z, xb.w};
            float wr[8] = {wa.x, wa.y, wa.z, wa.w, wb.x, wb.y, wb.z, wb.w};
#pragma unroll
            for (int i = 0; i < 8; i++)
#pragma unroll
                for (int j = 0; j < 8; j++)
                    acc[i][j] = fmaf(xr[i], wr[j], acc[i][j]);
        }
        __syncthreads();
    }

    float bs[8];
#pragma unroll
    for (int j = 0; j < 8; j++) {
        int cc = c0 + j;
        bs[j] = (cc < G_SZ) ? (b_ih[cc] + b_hh[cc]) : 0.f;
    }
#pragma unroll
    for (int i = 0; i < 8; i++) {
        int r = row0 + r0 + i;
        float4 lo = make_float4(acc[i][0] + bs[0], acc[i][1] + bs[1],
                                acc[i][2] + bs[2], acc[i][3] + bs[3]);
        float4 hi = make_float4(acc[i][4] + bs[4], acc[i][5] + bs[5],
                                acc[i][6] + bs[6], acc[i][7] + bs[7]);
        *(float4*)&g_xg[(size_t)r * XG_STRIDE + c0] = lo;
        *(float4*)&g_xg[(size_t)r * XG_STRIDE + c0 + 4] = hi;
    }
}

// =================================================================
// Kernel 2a: teacher-forced recurrence only. Block = batch, 128 thr
// (thread = gate row 4u+q), weights in regs, h via float4 LDS,
// 2 barriers/step. Tiny smem. Saves final state to g_state.
// =================================================================
__global__ __launch_bounds__(128, 1) void rec_teacher(
    const float* __restrict__ W_hh1, const float* __restrict__ W_ih2,
    const float* __restrict__ W_hh2, const float* __restrict__ b_ih2,
    const float* __restrict__ b_hh2) {
    __shared__ __align__(16) float h1a[32], h1b[32], h2s[32];

    const int tid = threadIdx.x;
    const int b = blockIdx.x;
    const int u = tid >> 2;
    const int q = tid & 3;
    const bool active = tid < G_SZ;
    const int srcrow = q * H_SZ + u;
    const int lanebase = (tid & 31) & ~3;
    const bool writer = (q == 0) && (u < H_SZ);

    float w1[32], w2a[32], w2b[32];
#pragma unroll
    for (int k = 0; k < 31; k++) {
        w1[k]  = active ? W_hh1[srcrow * H_SZ + k] : 0.f;
        w2a[k] = active ? W_ih2[srcrow * H_SZ + k] : 0.f;
        w2b[k] = active ? W_hh2[srcrow * H_SZ + k] : 0.f;
    }
    w1[31] = 0.f; w2a[31] = 0.f; w2b[31] = 0.f;
    const float myb2 = active ? (b_ih2[srcrow] + b_hh2[srcrow]) : 0.f;

    if (tid < 32) { h1a[tid] = 0.f; h1b[tid] = 0.f; h2s[tid] = 0.f; }
    float c1 = 0.f, c2 = 0.f;
    __syncthreads();

    const int xgcol = active ? srcrow : tid;
    const float* xgp = g_xg + (size_t)b * T_SZ * XG_STRIDE + xgcol;

    float* h1r = h1a;
    float* h1w = h1b;
    float h1 = 0.f, h2 = 0.f;

    float cur = __ldcg(xgp);

    for (int t = 0; t < T_SZ; t++) {
        float nxt = 0.f;
        if (t < T_SZ - 1) nxt = __ldcg(xgp + (size_t)(t + 1) * XG_STRIDE);

        // Phase A: layer-1 gate + layer-2 h2-part, act1
        float a  = cur + dot32q(w1, h1r);
        float d2 = myb2 + dot32q(w2b, h2s);
        float myg1 = (q == 2) ? tanh_f(a) : sigf(a);
        h1 = lstm_unit(myg1, lanebase, c1);
        if (writer) h1w[u] = h1;
        __syncthreads();

        // Phase B: layer-2 gate (h1 part), act2
        d2 += dot32q(w2a, h1w);
        float myg2 = (q == 2) ? tanh_f(d2) : sigf(d2);
        h2 = lstm_unit(myg2, lanebase, c2);
        if (writer) {
            h2s[u] = h2;
            g_h2hist[((size_t)b * T_SZ + t) * 32 + u] = h2;
        }
        cur = nxt;
        { float* tmp = h1r; h1r = h1w; h1w = tmp; }
        __syncthreads();
    }

    if (writer) {
        g_state[b][0][u] = h1;
        g_state[b][1][u] = c1;
        g_state[b][2][u] = h2;
        g_state[b][3][u] = c2;
    }
}

// =================================================================
// Kernel 2b: autoregressive future steps (16). Block = batch.
// =================================================================
#define FOFF_WLIN 0                     // k-major [32][1024] = 32768
#define FOFF_BLIN 32768                 // 1024
#define FOFF_XCUR 33792                 // 1024
#define FSM_FLOATS 34816
#define FSM_BYTES (FSM_FLOATS * 4)

__global__ __launch_bounds__(128, 1) void rec_future(
    const float* __restrict__ W_hh1, const float* __restrict__ W_ih2,
    const float* __restrict__ W_hh2, const float* __restrict__ b_ih2,
    const float* __restrict__ b_hh2, const float* __restrict__ W_ih1,
    const float* __restrict__ b_ih1, const float* __restrict__ b_hh1,
    const float* __restrict__ W_lin, const float* __restrict__ b_lin,
    float* __restrict__ out, int Tout, int future) {
    extern __shared__ float sm[];
    float* wlin_t = sm + FOFF_WLIN;
    float* blins  = sm + FOFF_BLIN;
    float* xcur   = sm + FOFF_XCUR;
    __shared__ __align__(16) float h1a[32], h1b[32], h2s[32];

    const int tid = threadIdx.x;
    const int b = blockIdx.x;
    const int u = tid >> 2;
    const int q = tid & 3;
    const bool active = tid < G_SZ;
    const int srcrow = q * H_SZ + u;
    const int lanebase = (tid & 31) & ~3;
    const bool writer = (q == 0) && (u < H_SZ);

    float w1[32], w2a[32], w2b[32];
#pragma unroll
    for (int k = 0; k < 31; k++) {
        w1[k]  = active ? W_hh1[srcrow * H_SZ + k] : 0.f;
        w2a[k] = active ? W_ih2[srcrow * H_SZ + k] : 0.f;
        w2b[k] = active ? W_hh2[srcrow * H_SZ + k] : 0.f;
    }
    w1[31] = 0.f; w2a[31] = 0.f; w2b[31] = 0.f;
    const float myb1 = active ? (b_ih1[srcrow] + b_hh1[srcrow]) : 0.f;
    const float myb2 = active ? (b_ih2[srcrow] + b_hh2[srcrow]) : 0.f;

    for (int i = tid; i < 32 * 1024; i += 128) {
        int k = i >> 10, f = i & 1023;
        wlin_t[i] = (k < H_SZ) ? W_lin[f * H_SZ + k] : 0.f;
    }
    for (int i = tid; i < 1024; i += 128) blins[i] = b_lin[i];
    if (tid < 32) { h1a[tid] = 0.f; h1b[tid] = 0.f; h2s[tid] = 0.f; }
    __syncthreads();
    if (tid < H_SZ) {
        h1a[tid] = g_state[b][0][tid];
        h2s[tid] = g_state[b][2][tid];
    }
    float c1 = (u < H_SZ) ? g_state[b][1][u] : 0.f;
    float c2 = (u < H_SZ) ? g_state[b][3][u] : 0.f;
    __syncthreads();

    float* h1r = h1a;
    float* h1w = h1b;
    float h1 = 0.f, h2 = 0.f;

    // xcur = output at t = T-1 (same value outproj writes at col 511)
#pragma unroll
    for (int i = 0; i < 8; i++) {
        int f = tid + i * 128;
        float a0 = blins[f], a1 = 0.f, a2 = 0.f, a3 = 0.f;
#pragma unroll
        for (int k = 0; k < 28; k += 4) {
            a0 = fmaf(wlin_t[(k + 0) * 1024 + f], h2s[k + 0], a0);
            a1 = fmaf(wlin_t[(k + 1) * 1024 + f], h2s[k + 1], a1);
            a2 = fmaf(wlin_t[(k + 2) * 1024 + f], h2s[k + 2], a2);
            a3 = fmaf(wlin_t[(k + 3) * 1024 + f], h2s[k + 3], a3);
        }
        a0 = fmaf(wlin_t[28 * 1024 + f], h2s[28], a0);
        a1 = fmaf(wlin_t[29 * 1024 + f], h2s[29], a1);
        a2 = fmaf(wlin_t[30 * 1024 + f], h2s[30], a2);
        xcur[f] = (a0 + a1) + (a2 + a3);
    }
    __syncthreads();

    for (int s = 1; s <= future; s++) {
        // Phase A: gates1 = W_ih1 row . xcur + W_hh1 . h1 + b1
        float a = myb1 + dot32q(w1, h1r);
        if (active) {
            const float4* w4 = (const float4*)(W_ih1 + (size_t)srcrow * F_SZ);
            const float4* x4 = (const float4*)xcur;
            float a0 = 0.f, a1 = 0.f, a2 = 0.f, a3 = 0.f;
#pragma unroll 8
            for (int p = 0; p < 256; p++) {
                float4 w = __ldcg(w4 + p);
                float4 xv = x4[p];
                a0 = fmaf(w.x, xv.x, a0);
                a1 = fmaf(w.y, xv.y, a1);
                a2 = fmaf(w.z, xv.z, a2);
                a3 = fmaf(w.w, xv.w, a3);
            }
            a += (a0 + a1) + (a2 + a3);
        }
        float d2 = myb2 + dot32q(w2b, h2s);
        float myg1 = (q == 2) ? tanh_f(a) : sigf(a);
        h1 = lstm_unit(myg1, lanebase, c1);
        if (writer) h1w[u] = h1;
        __syncthreads();

        // Phase B
        d2 += dot32q(w2a, h1w);
        float myg2 = (q == 2) ? tanh_f(d2) : sigf(d2);
        h2 = lstm_unit(myg2, lanebase, c2);
        if (writer) h2s[u] = h2;
        { float* tmp = h1r; h1r = h1w; h1w = tmp; }
        __syncthreads();

        // out_{511+s} = h2 . W_lin^T + b_lin ; also next x
#pragma unroll
        for (int i = 0; i < 8; i++) {
            int f = tid + i * 128;
            float a0 = blins[f], a1 = 0.f, a2 = 0.f, a3 = 0.f;
#pragma unroll
            for (int k = 0; k < 28; k += 4) {
                a0 = fmaf(wlin_t[(k + 0) * 1024 + f], h2s[k + 0], a0);
                a1 = fmaf(wlin_t[(k + 1) * 1024 + f], h2s[k + 1], a1);
                a2 = fmaf(wlin_t[(k + 2) * 1024 + f], h2s[k + 2], a2);
                a3 = fmaf(wlin_t[(k + 3) * 1024 + f], h2s[k + 3], a3);
            }
            a0 = fmaf(wlin_t[28 * 1024 + f], h2s[28], a0);
            a1 = fmaf(wlin_t[29 * 1024 + f], h2s[29], a1);
            a2 = fmaf(wlin_t[30 * 1024 + f], h2s[30], a2);
            float v = (a0 + a1) + (a2 + a3);
            xcur[f] = v;
            out[((size_t)b * Tout + (T_SZ - 1) + s) * F_SZ + f] = v;
        }
        __syncthreads();
    }
}

// =================================================================
// Kernel 3: teacher-forced output projection (unchanged)
// =================================================================
__global__ __launch_bounds__(256) void outproj_kernel(
    const float* __restrict__ W_lin, const float* __restrict__ b_lin,
    float* __restrict__ out, int Tout) {
    __shared__ float h2t[16][32];
    const int b = blockIdx.y;
    const int t0 = blockIdx.x * 16;
    const int tid = threadIdx.x;

    const float* src = g_h2hist + ((size_t)b * T_SZ + t0) * 32;
    for (int i = tid; i < 512; i += 256) ((float*)h2t)[i] = src[i];
    __syncthreads();

#pragma unroll
    for (int c = 0; c < 4; c++) {
        int f = tid + c * 256;
        float w[31];
        const float* wrow = W_lin + (size_t)f * 31;
#pragma unroll
        for (int k = 0; k < 31; k++) w[k] = wrow[k];
        float bv = b_lin[f];
#pragma unroll
        for (int tt = 0; tt < 16; tt++) {
            const float4* hp = (const float4*)&h2t[tt][0];
            float a0 = bv, a1 = 0.f, a2 = 0.f, a3 = 0.f;
#pragma unroll
            for (int p = 0; p < 7; p++) {
                float4 h = hp[p];
                a0 = fmaf(w[4 * p + 0], h.x, a0);
                a1 = fmaf(w[4 * p + 1], h.y, a1);
                a2 = fmaf(w[4 * p + 2], h.z, a2);
                a3 = fmaf(w[4 * p + 3], h.w, a3);
            }
            a0 = fmaf(w[28], h2t[tt][28], a0);
            a1 = fmaf(w[29], h2t[tt][29], a1);
            a2 = fmaf(w[30], h2t[tt][30], a2);
            out[((size_t)b * Tout + t0 + tt) * F_SZ + f] = (a0 + a1) + (a2 + a3);
        }
    }
}

// =================================================================
extern "C" void kernel_launch(void* const* d_in, const int* in_sizes, int n_in,
                              void* d_out, int out_size) {
    const float* input = (const float*)d_in[0];
    const float* W_ih1 = (const float*)d_in[1];
    const float* W_hh1 = (const float*)d_in[2];
    const float* b_ih1 = (const float*)d_in[3];
    const float* b_hh1 = (const float*)d_in[4];
    const float* W_ih2 = (const float*)d_in[5];
    const float* W_hh2 = (const float*)d_in[6];
    const float* b_ih2 = (const float*)d_in[7];
    const float* b_hh2 = (const float*)d_in[8];
    const float* W_lin = (const float*)d_in[9];
    const float* b_lin = (const float*)d_in[10];
    float* out = (float*)d_out;

    const int Tout = out_size / (B_SZ * F_SZ);   // 528
    const int future = Tout - T_SZ;              // 16

    cudaFuncSetAttribute(rec_future,
                         cudaFuncAttributeMaxDynamicSharedMemorySize, FSM_BYTES);

    gemm_xg_kernel<<<ROWS / 128, 256>>>(input, W_ih1, b_ih1, b_hh1);

    rec_teacher<<<B_SZ, 128>>>(W_hh1, W_ih2, W_hh2, b_ih2, b_hh2);

    rec_future<<<B_SZ, 128, FSM_BYTES>>>(
        W_hh1, W_ih2, W_hh2, b_ih2, b_hh2, W_ih1, b_ih1, b_hh1,
        W_lin, b_lin, out, Tout, future);

    dim3 g3(T_SZ / 16, B_SZ);
    outproj_kernel<<<g3, 256>>>(W_lin, b_lin, out, Tout);
}